// round 4
// baseline (speedup 1.0000x reference)
#include <cuda_runtime.h>

// Polar decomposition of A = rotation[n] @ mat. 4 matrices per thread as two
// independent f32x2-packed chains (ILP=2). Head: det-scaled Newton
//   X <- 0.5*g*X + 0.5*g^2*sign(det)*cof(X),  g=|det|^(-1/3)
// Tail: Newton-Schulz X <- X(3I - X^T X)/2 (pure FMA2, no MUFU), guarded by
// tr(X^T X) < 4.5 (=> sigma_max < sqrt(3)); convergence via tr -> 3.

#define TPB 128
#define MPT 4
typedef unsigned long long u64;

__device__ __forceinline__ u64 f2pack(float lo, float hi) {
    u64 r; asm("mov.b64 %0, {%1, %2};" : "=l"(r) : "f"(lo), "f"(hi)); return r;
}
__device__ __forceinline__ void f2unpack(u64 v, float& lo, float& hi) {
    asm("mov.b64 {%0, %1}, %2;" : "=f"(lo), "=f"(hi) : "l"(v));
}
__device__ __forceinline__ u64 f2mul(u64 a, u64 b) {
    u64 d; asm("mul.rn.f32x2 %0, %1, %2;" : "=l"(d) : "l"(a), "l"(b)); return d;
}
__device__ __forceinline__ u64 f2add(u64 a, u64 b) {
    u64 d; asm("add.rn.f32x2 %0, %1, %2;" : "=l"(d) : "l"(a), "l"(b)); return d;
}
__device__ __forceinline__ u64 f2fma(u64 a, u64 b, u64 c) {
    u64 d; asm("fma.rn.f32x2 %0, %1, %2, %3;" : "=l"(d) : "l"(a), "l"(b), "l"(c)); return d;
}
__device__ __forceinline__ u64 f2neg(u64 a) { return a ^ 0x8000000080000000ULL; }
__device__ __forceinline__ u64 f2msub(u64 a, u64 b, u64 c, u64 d) {
    return f2fma(a, b, f2neg(f2mul(c, d)));
}
__device__ __forceinline__ float lg2_fast(float x) {
    float r; asm("lg2.approx.f32 %0, %1;" : "=f"(r) : "f"(x)); return r;
}
__device__ __forceinline__ float ex2_fast(float x) {
    float r; asm("ex2.approx.f32 %0, %1;" : "=f"(r) : "f"(x)); return r;
}

struct P2 { u64 x0,x1,x2,x3,x4,x5,x6,x7,x8; };

// One det-scaled Newton step (rcp-free): uses det(gX) = sign(det) exactly.
__device__ __forceinline__ void newton_step(P2& X) {
    const u64 c00 = f2msub(X.x4, X.x8, X.x5, X.x7);
    const u64 c01 = f2msub(X.x5, X.x6, X.x3, X.x8);
    const u64 c02 = f2msub(X.x3, X.x7, X.x4, X.x6);
    const u64 c10 = f2msub(X.x2, X.x7, X.x1, X.x8);
    const u64 c11 = f2msub(X.x0, X.x8, X.x2, X.x6);
    const u64 c12 = f2msub(X.x1, X.x6, X.x0, X.x7);
    const u64 c20 = f2msub(X.x1, X.x5, X.x2, X.x4);
    const u64 c21 = f2msub(X.x2, X.x3, X.x0, X.x5);
    const u64 c22 = f2msub(X.x0, X.x4, X.x1, X.x3);
    const u64 det = f2fma(X.x0, c00, f2fma(X.x1, c01, f2mul(X.x2, c02)));

    float dl, dh;
    f2unpack(det, dl, dh);
    const float gl = ex2_fast(-0.33333333f * lg2_fast(fmaxf(fabsf(dl), 1e-36f)));
    const float gh = ex2_fast(-0.33333333f * lg2_fast(fmaxf(fabsf(dh), 1e-36f)));
    const float rl = copysignf(0.5f * gl * gl, dl);
    const float rh = copysignf(0.5f * gh * gh, dh);
    const u64 hg = f2pack(0.5f * gl, 0.5f * gh);
    const u64 rr = f2pack(rl, rh);

    X.x0 = f2fma(rr, c00, f2mul(hg, X.x0));
    X.x1 = f2fma(rr, c01, f2mul(hg, X.x1));
    X.x2 = f2fma(rr, c02, f2mul(hg, X.x2));
    X.x3 = f2fma(rr, c10, f2mul(hg, X.x3));
    X.x4 = f2fma(rr, c11, f2mul(hg, X.x4));
    X.x5 = f2fma(rr, c12, f2mul(hg, X.x5));
    X.x6 = f2fma(rr, c20, f2mul(hg, X.x6));
    X.x7 = f2fma(rr, c21, f2mul(hg, X.x7));
    X.x8 = f2fma(rr, c22, f2mul(hg, X.x8));
}

// Gram matrix B = X^T X (6 unique entries) and its trace.
__device__ __forceinline__ void gram(const P2& X, u64 B[6], u64& tr) {
    B[0] = f2fma(X.x0, X.x0, f2fma(X.x3, X.x3, f2mul(X.x6, X.x6)));  // b00
    B[1] = f2fma(X.x0, X.x1, f2fma(X.x3, X.x4, f2mul(X.x6, X.x7)));  // b01
    B[2] = f2fma(X.x0, X.x2, f2fma(X.x3, X.x5, f2mul(X.x6, X.x8)));  // b02
    B[3] = f2fma(X.x1, X.x1, f2fma(X.x4, X.x4, f2mul(X.x7, X.x7)));  // b11
    B[4] = f2fma(X.x1, X.x2, f2fma(X.x4, X.x5, f2mul(X.x7, X.x8)));  // b12
    B[5] = f2fma(X.x2, X.x2, f2fma(X.x5, X.x5, f2mul(X.x8, X.x8)));  // b22
    tr = f2add(B[0], f2add(B[3], B[5]));
}

// Newton-Schulz update: X <- X @ (1.5 I - 0.5 B), B symmetric.
__device__ __forceinline__ void ns_update(P2& X, const u64 B[6]) {
    const u64 c15  = f2pack(1.5f, 1.5f);
    const u64 cm05 = f2pack(-0.5f, -0.5f);
    const u64 p00 = f2fma(B[0], cm05, c15);
    const u64 p01 = f2mul(B[1], cm05);
    const u64 p02 = f2mul(B[2], cm05);
    const u64 p11 = f2fma(B[3], cm05, c15);
    const u64 p12 = f2mul(B[4], cm05);
    const u64 p22 = f2fma(B[5], cm05, c15);

    const u64 y0 = f2fma(X.x0, p00, f2fma(X.x1, p01, f2mul(X.x2, p02)));
    const u64 y1 = f2fma(X.x0, p01, f2fma(X.x1, p11, f2mul(X.x2, p12)));
    const u64 y2 = f2fma(X.x0, p02, f2fma(X.x1, p12, f2mul(X.x2, p22)));
    const u64 y3 = f2fma(X.x3, p00, f2fma(X.x4, p01, f2mul(X.x5, p02)));
    const u64 y4 = f2fma(X.x3, p01, f2fma(X.x4, p11, f2mul(X.x5, p12)));
    const u64 y5 = f2fma(X.x3, p02, f2fma(X.x4, p12, f2mul(X.x5, p22)));
    const u64 y6 = f2fma(X.x6, p00, f2fma(X.x7, p01, f2mul(X.x8, p02)));
    const u64 y7 = f2fma(X.x6, p01, f2fma(X.x7, p11, f2mul(X.x8, p12)));
    const u64 y8 = f2fma(X.x6, p02, f2fma(X.x7, p12, f2mul(X.x8, p22)));
    X.x0 = y0; X.x1 = y1; X.x2 = y2;
    X.x3 = y3; X.x4 = y4; X.x5 = y5;
    X.x6 = y6; X.x7 = y7; X.x8 = y8;
}

__device__ __forceinline__ P2 mul_rm(const u64 R[9], const u64 M[9]) {
    P2 X;
    X.x0 = f2fma(R[0], M[0], f2fma(R[1], M[3], f2mul(R[2], M[6])));
    X.x1 = f2fma(R[0], M[1], f2fma(R[1], M[4], f2mul(R[2], M[7])));
    X.x2 = f2fma(R[0], M[2], f2fma(R[1], M[5], f2mul(R[2], M[8])));
    X.x3 = f2fma(R[3], M[0], f2fma(R[4], M[3], f2mul(R[5], M[6])));
    X.x4 = f2fma(R[3], M[1], f2fma(R[4], M[4], f2mul(R[5], M[7])));
    X.x5 = f2fma(R[3], M[2], f2fma(R[4], M[5], f2mul(R[5], M[8])));
    X.x6 = f2fma(R[6], M[0], f2fma(R[7], M[3], f2mul(R[8], M[6])));
    X.x7 = f2fma(R[6], M[1], f2fma(R[7], M[4], f2mul(R[8], M[7])));
    X.x8 = f2fma(R[6], M[2], f2fma(R[7], M[5], f2mul(R[8], M[8])));
    return X;
}

__global__ void __launch_bounds__(TPB)
polar4_kernel(const float* __restrict__ rot,
              const float* __restrict__ mat,
              float* __restrict__ out,
              float* __restrict__ logdet,
              int N)
{
    const int t  = blockIdx.x * TPB + threadIdx.x;
    const int g0 = t * MPT;                       // first of this thread's 4 matrices
    const bool full = (g0 + MPT) <= N;

    // broadcast learned matrix, packed
    u64 M[9];
    #pragma unroll
    for (int k = 0; k < 9; ++k) { const float m = __ldg(mat + k); M[k] = f2pack(m, m); }

    // ---- load 4 matrices = 36 floats = 9 float4 (fully coalesced) ----
    float a[36];
    if (full) {
        const float4* p = reinterpret_cast<const float4*>(rot + (size_t)g0 * 9);
        #pragma unroll
        for (int i = 0; i < 9; ++i) {
            const float4 v = p[i];
            a[4*i+0] = v.x; a[4*i+1] = v.y; a[4*i+2] = v.z; a[4*i+3] = v.w;
        }
    } else {
        #pragma unroll
        for (int k = 0; k < 36; ++k) {
            const int m = g0 + k / 9, e = k % 9;
            const float idv = (e == 0 || e == 4 || e == 8) ? 1.0f : 0.0f;
            a[k] = (m < N) ? rot[(size_t)g0 * 9 + k] : idv;
        }
    }

    // pack into two chains: A = (mat0, mat1), B = (mat2, mat3)
    u64 RA[9], RB[9];
    #pragma unroll
    for (int k = 0; k < 9; ++k) {
        RA[k] = f2pack(a[k],      a[9  + k]);
        RB[k] = f2pack(a[18 + k], a[27 + k]);
    }

    P2 XA = mul_rm(RA, M);
    P2 XB = mul_rm(RB, M);

    // ---- head: 3 det-scaled Newton steps, no checks ----
    #pragma unroll
    for (int it = 0; it < 3; ++it) { newton_step(XA); newton_step(XB); }

    // ---- adaptive tail: Newton-Schulz when safe, else another scaled step ----
    #pragma unroll 1
    for (int it = 0; it < 8; ++it) {
        u64 BA[6], BB[6], trA, trB;
        gram(XA, BA, trA);
        gram(XB, BB, trB);
        float ta0, ta1, tb0, tb1;
        f2unpack(trA, ta0, ta1);
        f2unpack(trB, tb0, tb1);
        const float err = fmaxf(fmaxf(fabsf(ta0 - 3.0f), fabsf(ta1 - 3.0f)),
                                fmaxf(fabsf(tb0 - 3.0f), fabsf(tb1 - 3.0f)));
        if (__all_sync(0xffffffffu, err < 3e-4f)) break;
        const float mx = fmaxf(fmaxf(ta0, ta1), fmaxf(tb0, tb1));
        if (__all_sync(0xffffffffu, mx < 4.5f)) {
            ns_update(XA, BA);
            ns_update(XB, BB);
        } else {
            newton_step(XA);
            newton_step(XB);
        }
    }

    // ---- store ----
    float b[36];
    f2unpack(XA.x0, b[0], b[9]);   f2unpack(XA.x1, b[1], b[10]);
    f2unpack(XA.x2, b[2], b[11]);  f2unpack(XA.x3, b[3], b[12]);
    f2unpack(XA.x4, b[4], b[13]);  f2unpack(XA.x5, b[5], b[14]);
    f2unpack(XA.x6, b[6], b[15]);  f2unpack(XA.x7, b[7], b[16]);
    f2unpack(XA.x8, b[8], b[17]);
    f2unpack(XB.x0, b[18], b[27]); f2unpack(XB.x1, b[19], b[28]);
    f2unpack(XB.x2, b[20], b[29]); f2unpack(XB.x3, b[21], b[30]);
    f2unpack(XB.x4, b[22], b[31]); f2unpack(XB.x5, b[23], b[32]);
    f2unpack(XB.x6, b[24], b[33]); f2unpack(XB.x7, b[25], b[34]);
    f2unpack(XB.x8, b[26], b[35]);

    if (full) {
        float4* p = reinterpret_cast<float4*>(out + (size_t)g0 * 9);
        #pragma unroll
        for (int i = 0; i < 9; ++i)
            p[i] = make_float4(b[4*i+0], b[4*i+1], b[4*i+2], b[4*i+3]);
        *reinterpret_cast<float4*>(logdet + g0) = make_float4(0.f, 0.f, 0.f, 0.f);
    } else {
        #pragma unroll
        for (int k = 0; k < 36; ++k) {
            const int m = g0 + k / 9;
            if (m < N) out[(size_t)g0 * 9 + k] = b[k];
        }
        #pragma unroll
        for (int j = 0; j < MPT; ++j)
            if (g0 + j < N) logdet[g0 + j] = 0.0f;
    }
}

__global__ void zero_tail_kernel(float* __restrict__ p, long long n)
{
    long long i = (long long)blockIdx.x * blockDim.x + threadIdx.x;
    if (i < n) p[i] = 0.0f;
}

extern "C" void kernel_launch(void* const* d_in, const int* in_sizes, int n_in,
                              void* d_out, int out_size)
{
    const float* rot = (const float*)d_in[0];
    const float* mat = (const float*)d_in[1];
    float* out = (float*)d_out;

    const int N = in_sizes[0] / 9;
    float* logdet = out + (size_t)N * 9;

    const int mats_per_block = TPB * MPT;
    const int blocks = (N + mats_per_block - 1) / mats_per_block;
    polar4_kernel<<<blocks, TPB>>>(rot, mat, out, logdet, N);

    const long long used = 10LL * N;
    if ((long long)out_size > used) {
        const long long extra = (long long)out_size - used;
        const int zb = (int)((extra + 255) / 256);
        zero_tail_kernel<<<zb, 256>>>(out + used, extra);
    }
}